// round 7
// baseline (speedup 1.0000x reference)
#include <cuda_runtime.h>
#include <cuda_fp16.h>

// ---------------------------------------------------------------------------
// HMPNN layer, R6: R4 structure (U-table + fp16 gather + red.v4 scatter),
// prep/final parallelized, launch order tuned so profiler lands on edge_a.
//   U[n,f,o] = sum_i x_src[n,i] * w_msg[f,i,o]   (f=16 block = xj@b_msg)
//   msg[e,o] = U[src,16,o] + sum_f ea[e,f] * U[src,f,o]
//   agg[n]   = segment_sum(msg) + x_indivi @ root + bias
//   out      = sigmoid( concat(sig(agg_a), sig(agg_b)) @ w_lin + b_lin )
// ---------------------------------------------------------------------------

#define NMAX 50000
#define UROW 272              // 17 f-blocks * 16 outputs

__device__ float  g_agg[2][NMAX * 16];
__device__ __half g_U[2][NMAX * UROW];

__device__ __forceinline__ void red4(float* p, float a, float b, float c, float d) {
    asm volatile("red.global.add.v4.f32 [%0], {%1,%2,%3,%4};"
                 :: "l"(p), "f"(a), "f"(b), "f"(c), "f"(d) : "memory");
}
__device__ __forceinline__ float sigmoidf(float x) {
    return 1.0f / (1.0f + __expf(-x));
}

// ---------------------------------------------------------------------------
// init: 2 threads per node (lane = step): agg[step][n] = bias + x_indivi@root
// ---------------------------------------------------------------------------
__global__ __launch_bounds__(256) void init_kernel(
    const float* __restrict__ x_indivi,
    const float* __restrict__ root_a, const float* __restrict__ bias_a,
    const float* __restrict__ root_b, const float* __restrict__ bias_b,
    int N) {
    int t = blockIdx.x * 256 + threadIdx.x;
    int n = t >> 1;
    int step = t & 1;
    if (n >= N) return;
    const float* __restrict__ root = step ? root_b : root_a;
    const float* __restrict__ bias = step ? bias_b : bias_a;

    float x[16];
    const float4* xr = (const float4*)(x_indivi + n * 16);
#pragma unroll
    for (int j = 0; j < 4; ++j) {
        float4 v = xr[j];
        x[4 * j + 0] = v.x; x[4 * j + 1] = v.y;
        x[4 * j + 2] = v.z; x[4 * j + 3] = v.w;
    }
    float s[16];
#pragma unroll
    for (int o = 0; o < 16; ++o) s[o] = __ldg(bias + o);
#pragma unroll
    for (int i = 0; i < 16; ++i) {
        float xi = x[i];
        const float4* rr = (const float4*)(root + i * 16);
#pragma unroll
        for (int j = 0; j < 4; ++j) {
            float4 w = __ldg(rr + j);
            s[4 * j + 0] += xi * w.x;
            s[4 * j + 1] += xi * w.y;
            s[4 * j + 2] += xi * w.z;
            s[4 * j + 3] += xi * w.w;
        }
    }
    float4* dst = (float4*)(&g_agg[step][n * 16]);
#pragma unroll
    for (int j = 0; j < 4; ++j)
        dst[j] = make_float4(s[4 * j], s[4 * j + 1], s[4 * j + 2], s[4 * j + 3]);
}

// ---------------------------------------------------------------------------
// u_kernel: 2 threads per node; lane 0 -> f-blocks 0..8, lane 1 -> 9..16
// ---------------------------------------------------------------------------
__global__ __launch_bounds__(256) void u_kernel(
    const float* __restrict__ xs,
    const float* __restrict__ wm,
    const float* __restrict__ bm,
    __half* __restrict__ U,
    int N) {
    __shared__ __align__(16) float Ws[17 * 256];   // [f][i][o], f=16 = b_msg
    for (int k = threadIdx.x; k < 4096; k += 256) Ws[k] = wm[k];
    for (int k = threadIdx.x; k < 256; k += 256) Ws[4096 + k] = bm[k];
    {
        int k = 256 + threadIdx.x;
        if (k < 256) {}
    }
    // second chunk of bm
    if (threadIdx.x < 0) {}
    for (int k = 256 + threadIdx.x; k < 256; k += 256) {}
    __syncthreads();

    int t = blockIdx.x * 256 + threadIdx.x;
    int n = t >> 1;
    int l = t & 1;
    if (n >= N) return;

    float x[16];
    const float4* xr = (const float4*)(xs + n * 16);
#pragma unroll
    for (int j = 0; j < 4; ++j) {
        float4 v = xr[j];
        x[4 * j + 0] = v.x; x[4 * j + 1] = v.y;
        x[4 * j + 2] = v.z; x[4 * j + 3] = v.w;
    }

    int f0 = l ? 9 : 0;
    int f1 = l ? 17 : 9;
    __half* Urow = U + n * UROW;
#pragma unroll 1
    for (int f = f0; f < f1; ++f) {
        const float* Wf = Ws + f * 256;
        float acc[16];
#pragma unroll
        for (int o = 0; o < 16; ++o) acc[o] = 0.0f;
#pragma unroll
        for (int i = 0; i < 16; ++i) {
            float xi = x[i];
            const float4* wr = (const float4*)(Wf + i * 16);
#pragma unroll
            for (int j = 0; j < 4; ++j) {
                float4 w = wr[j];
                acc[4 * j + 0] += xi * w.x;
                acc[4 * j + 1] += xi * w.y;
                acc[4 * j + 2] += xi * w.z;
                acc[4 * j + 3] += xi * w.w;
            }
        }
        __half2 h[8];
#pragma unroll
        for (int j = 0; j < 8; ++j)
            h[j] = __floats2half2_rn(acc[2 * j], acc[2 * j + 1]);
        uint4* dst = (uint4*)(Urow + f * 16);
        dst[0] = *(const uint4*)&h[0];
        dst[1] = *(const uint4*)&h[4];
    }
}

// ---------------------------------------------------------------------------
// edge: 2 lanes per edge; lane l owns outputs 8l..8l+7 (one LDG.128 per f)
// ---------------------------------------------------------------------------
__global__ __launch_bounds__(256) void edge_kernel(
    const int* __restrict__ ei,
    const float* __restrict__ eat,
    const __half* __restrict__ U,
    float* __restrict__ agg,
    int E) {
    int t = blockIdx.x * 256 + threadIdx.x;
    int e = t >> 1;
    int l = t & 1;
    if (e >= E) return;

    int s = __ldg(ei + e);
    int d = __ldg(ei + E + e);

    const uint4* __restrict__ Ur = (const uint4*)(U + s * UROW) + l;  // 16B units
    const float4* __restrict__ ear = (const float4*)(eat + e * 16);

    float4 ea0 = __ldg(ear + 0);
    float4 ea1 = __ldg(ear + 1);
    float4 ea2 = __ldg(ear + 2);
    float4 ea3 = __ldg(ear + 3);
    float ea[16] = {ea0.x, ea0.y, ea0.z, ea0.w,
                    ea1.x, ea1.y, ea1.z, ea1.w,
                    ea2.x, ea2.y, ea2.z, ea2.w,
                    ea3.x, ea3.y, ea3.z, ea3.w};

    float4 accL, accH;
    {
        uint4 u = __ldg(Ur + 32);   // bias block f=16
        const __half2* h = (const __half2*)&u;
        float2 f0 = __half22float2(h[0]);
        float2 f1 = __half22float2(h[1]);
        float2 f2 = __half22float2(h[2]);
        float2 f3 = __half22float2(h[3]);
        accL = make_float4(f0.x, f0.y, f1.x, f1.y);
        accH = make_float4(f2.x, f2.y, f3.x, f3.y);
    }

#pragma unroll
    for (int r = 0; r < 16; ++r) {
        uint4 u = __ldg(Ur + r * 2);
        float er = ea[r];
        const __half2* h = (const __half2*)&u;
        float2 f0 = __half22float2(h[0]);
        float2 f1 = __half22float2(h[1]);
        float2 f2 = __half22float2(h[2]);
        float2 f3 = __half22float2(h[3]);
        accL.x += er * f0.x; accL.y += er * f0.y;
        accL.z += er * f1.x; accL.w += er * f1.y;
        accH.x += er * f2.x; accH.y += er * f2.y;
        accH.z += er * f3.x; accH.w += er * f3.y;
    }

    float* base = &agg[d * 16 + 8 * l];
    red4(base,     accL.x, accL.y, accL.z, accL.w);
    red4(base + 4, accH.x, accH.y, accH.z, accH.w);
}

// ---------------------------------------------------------------------------
// final: 2 lanes per node; lane l computes outputs 16l..16l+15
// ---------------------------------------------------------------------------
__global__ __launch_bounds__(256) void final_kernel(
    const float* __restrict__ w_lin,
    const float* __restrict__ b_lin,
    float* __restrict__ out, int N) {
    __shared__ __align__(16) float wl[32 * 32];
    __shared__ float bl[32];
    for (int k = threadIdx.x; k < 1024; k += 256) wl[k] = w_lin[k];
    if (threadIdx.x < 32) bl[threadIdx.x] = b_lin[threadIdx.x];
    __syncthreads();

    int t = blockIdx.x * 256 + threadIdx.x;
    int n = t >> 1;
    int l = t & 1;
    if (n >= N) return;

    float s[32];
    {
        const float4* ga = (const float4*)(&g_agg[0][n * 16]);
        const float4* gb = (const float4*)(&g_agg[1][n * 16]);
#pragma unroll
        for (int j = 0; j < 4; ++j) {
            float4 va = ga[j];
            s[4 * j + 0] = sigmoidf(va.x); s[4 * j + 1] = sigmoidf(va.y);
            s[4 * j + 2] = sigmoidf(va.z); s[4 * j + 3] = sigmoidf(va.w);
        }
#pragma unroll
        for (int j = 0; j < 4; ++j) {
            float4 vb = gb[j];
            s[16 + 4 * j + 0] = sigmoidf(vb.x); s[16 + 4 * j + 1] = sigmoidf(vb.y);
            s[16 + 4 * j + 2] = sigmoidf(vb.z); s[16 + 4 * j + 3] = sigmoidf(vb.w);
        }
    }

    float4 acc[4];
#pragma unroll
    for (int j = 0; j < 4; ++j) {
        int o = 16 * l + 4 * j;
        acc[j] = make_float4(bl[o], bl[o + 1], bl[o + 2], bl[o + 3]);
    }
#pragma unroll
    for (int k = 0; k < 32; ++k) {
        float sk = s[k];
        const float4* w4 = (const float4*)(wl + k * 32 + 16 * l);
#pragma unroll
        for (int j = 0; j < 4; ++j) {
            float4 w = w4[j];
            acc[j].x += sk * w.x;
            acc[j].y += sk * w.y;
            acc[j].z += sk * w.z;
            acc[j].w += sk * w.w;
        }
    }

    float4* o4 = (float4*)(out + n * 32 + 16 * l);
#pragma unroll
    for (int j = 0; j < 4; ++j)
        o4[j] = make_float4(sigmoidf(acc[j].x), sigmoidf(acc[j].y),
                            sigmoidf(acc[j].z), sigmoidf(acc[j].w));
}

// ---------------------------------------------------------------------------
extern "C" void kernel_launch(void* const* d_in, const int* in_sizes, int n_in,
                              void* d_out, int out_size) {
    const float* x_indivi = (const float*)d_in[0];
    const float* x_src_a  = (const float*)d_in[1];
    const float* x_src_b  = (const float*)d_in[2];
    const int*   ei_a     = (const int*)d_in[3];
    const int*   ei_b     = (const int*)d_in[4];
    const float* ea_a     = (const float*)d_in[5];
    const float* ea_b     = (const float*)d_in[6];
    const float* wm_a     = (const float*)d_in[7];
    const float* bm_a     = (const float*)d_in[8];
    const float* root_a   = (const float*)d_in[9];
    const float* bias_a   = (const float*)d_in[10];
    const float* wm_b     = (const float*)d_in[11];
    const float* bm_b     = (const float*)d_in[12];
    const float* root_b   = (const float*)d_in[13];
    const float* bias_b   = (const float*)d_in[14];
    const float* w_lin    = (const float*)d_in[15];
    const float* b_lin    = (const float*)d_in[16];
    float* out = (float*)d_out;

    int N = in_sizes[0] / 16;
    int E = in_sizes[3] / 2;   // edge_index is [2, E]

    float* agg_base;  __half* U_base;
    cudaGetSymbolAddress((void**)&agg_base, g_agg);
    cudaGetSymbolAddress((void**)&U_base, g_U);
    float*  agg_a = agg_base;
    float*  agg_b = agg_base + NMAX * 16;
    __half* U_a = U_base;
    __half* U_b = U_base + NMAX * UROW;

    int nb2 = (2 * N + 255) / 256;
    int eb2 = (2 * E + 255) / 256;

    // launch 1: init
    init_kernel<<<nb2, 256>>>(x_indivi, root_a, bias_a, root_b, bias_b, N);
    // launch 2,3: U tables
    u_kernel<<<nb2, 256>>>(x_src_a, wm_a, bm_a, U_a, N);
    u_kernel<<<nb2, 256>>>(x_src_b, wm_b, bm_b, U_b, N);
    // launch 4: edge step a  (profiler has landed on launch #4 every round)
    edge_kernel<<<eb2, 256>>>(ei_a, ea_a, U_a, agg_a, E);
    // launch 5: edge step b
    edge_kernel<<<eb2, 256>>>(ei_b, ea_b, U_b, agg_b, E);
    // launch 6: final
    final_kernel<<<nb2, 256>>>(w_lin, b_lin, out, N);
}

// round 9
// speedup vs baseline: 1.6843x; 1.6843x over previous
#include <cuda_runtime.h>
#include <cuda_fp16.h>

// ---------------------------------------------------------------------------
// HMPNN layer, R7: U-table factorization; edge gather coalesced at 128B-line
// granularity (8 lanes per edge, padded 640B U rows), fp16 U, red.v4 scatter.
//   U[n,f,o] = sum_i x_src[n,i] * w_msg[f,i,o]   (f=16 block = xj@b_msg)
//   msg[e,o] = U[src,16,o] + sum_f ea[e,f] * U[src,f,o]
//   agg[n]   = segment_sum(msg) + x_indivi @ root + bias
//   out      = sigmoid( concat(sig(agg_a), sig(agg_b)) @ w_lin + b_lin )
// ---------------------------------------------------------------------------

#define NMAX 50000
#define UROWP 320            // padded row: 320 halves = 640B = 5 x 128B lines

__device__ float  g_agg[2][NMAX * 16];
__device__ __align__(128) __half g_U[2][NMAX * UROWP];

__device__ __forceinline__ void red4(float* p, float a, float b, float c, float d) {
    asm volatile("red.global.add.v4.f32 [%0], {%1,%2,%3,%4};"
                 :: "l"(p), "f"(a), "f"(b), "f"(c), "f"(d) : "memory");
}
__device__ __forceinline__ float sigmoidf(float x) {
    return 1.0f / (1.0f + __expf(-x));
}

// ---------------------------------------------------------------------------
// init: 2 threads per node (lane = step): agg[step][n] = bias + x_indivi@root
// ---------------------------------------------------------------------------
__global__ __launch_bounds__(256) void init_kernel(
    const float* __restrict__ x_indivi,
    const float* __restrict__ root_a, const float* __restrict__ bias_a,
    const float* __restrict__ root_b, const float* __restrict__ bias_b,
    int N) {
    int t = blockIdx.x * 256 + threadIdx.x;
    int n = t >> 1;
    int step = t & 1;
    if (n >= N) return;
    const float* __restrict__ root = step ? root_b : root_a;
    const float* __restrict__ bias = step ? bias_b : bias_a;

    float x[16];
    const float4* xr = (const float4*)(x_indivi + n * 16);
#pragma unroll
    for (int j = 0; j < 4; ++j) {
        float4 v = xr[j];
        x[4 * j + 0] = v.x; x[4 * j + 1] = v.y;
        x[4 * j + 2] = v.z; x[4 * j + 3] = v.w;
    }
    float s[16];
#pragma unroll
    for (int o = 0; o < 16; ++o) s[o] = __ldg(bias + o);
#pragma unroll
    for (int i = 0; i < 16; ++i) {
        float xi = x[i];
        const float4* rr = (const float4*)(root + i * 16);
#pragma unroll
        for (int j = 0; j < 4; ++j) {
            float4 w = __ldg(rr + j);
            s[4 * j + 0] += xi * w.x;
            s[4 * j + 1] += xi * w.y;
            s[4 * j + 2] += xi * w.z;
            s[4 * j + 3] += xi * w.w;
        }
    }
    float4* dst = (float4*)(&g_agg[step][n * 16]);
#pragma unroll
    for (int j = 0; j < 4; ++j)
        dst[j] = make_float4(s[4 * j], s[4 * j + 1], s[4 * j + 2], s[4 * j + 3]);
}

// ---------------------------------------------------------------------------
// u_kernel: 2 threads per node; lane 0 -> f-blocks 0..8, lane 1 -> 9..16
// writes padded rows (stride UROWP halves)
// ---------------------------------------------------------------------------
__global__ __launch_bounds__(256) void u_kernel(
    const float* __restrict__ xs,
    const float* __restrict__ wm,
    const float* __restrict__ bm,
    __half* __restrict__ U,
    int N) {
    __shared__ __align__(16) float Ws[17 * 256];   // [f][i][o], f=16 = b_msg
    for (int k = threadIdx.x; k < 4096; k += 256) Ws[k] = wm[k];
    if (threadIdx.x < 256) Ws[4096 + threadIdx.x] = bm[threadIdx.x];
    __syncthreads();

    int t = blockIdx.x * 256 + threadIdx.x;
    int n = t >> 1;
    int l = t & 1;
    if (n >= N) return;

    float x[16];
    const float4* xr = (const float4*)(xs + n * 16);
#pragma unroll
    for (int j = 0; j < 4; ++j) {
        float4 v = xr[j];
        x[4 * j + 0] = v.x; x[4 * j + 1] = v.y;
        x[4 * j + 2] = v.z; x[4 * j + 3] = v.w;
    }

    int f0 = l ? 9 : 0;
    int f1 = l ? 17 : 9;
    __half* Urow = U + (long)n * UROWP;
#pragma unroll 1
    for (int f = f0; f < f1; ++f) {
        const float* Wf = Ws + f * 256;
        float acc[16];
#pragma unroll
        for (int o = 0; o < 16; ++o) acc[o] = 0.0f;
#pragma unroll
        for (int i = 0; i < 16; ++i) {
            float xi = x[i];
            const float4* wr = (const float4*)(Wf + i * 16);
#pragma unroll
            for (int j = 0; j < 4; ++j) {
                float4 w = wr[j];
                acc[4 * j + 0] += xi * w.x;
                acc[4 * j + 1] += xi * w.y;
                acc[4 * j + 2] += xi * w.z;
                acc[4 * j + 3] += xi * w.w;
            }
        }
        __half2 h[8];
#pragma unroll
        for (int j = 0; j < 8; ++j)
            h[j] = __floats2half2_rn(acc[2 * j], acc[2 * j + 1]);
        uint4* dst = (uint4*)(Urow + f * 16);
        dst[0] = *(const uint4*)&h[0];
        dst[1] = *(const uint4*)&h[4];
    }
}

// ---------------------------------------------------------------------------
// edge: 8 lanes per edge. Round c (0..3): octet loads one full 128B line
// (f-blocks 4c..4c+3); lane j owns f = 4c + (j>>1), o-half h = j&1.
// Round 4: lanes 0/1 load the bias block (f=16, first 32B of line 4).
// Butterfly shfl_xor(2),(4) reduces partial f-sums within each o-half group.
// ---------------------------------------------------------------------------
__global__ __launch_bounds__(256) void edge_kernel(
    const int* __restrict__ ei,
    const float* __restrict__ eat,
    const __half* __restrict__ U,
    float* __restrict__ agg,
    int E) {
    int t = blockIdx.x * 256 + threadIdx.x;
    int g = t >> 3;                 // edge index
    int j = t & 7;                  // octet lane
    bool valid = (g < E);
    if (g >= E) g = E - 1;          // clamp; keep all lanes converged for shfl

    int h = j & 1;                  // o-half (0: o0..7, 1: o8..15)
    int fi = j >> 1;                // f offset within each 4-block

    int s = __ldg(ei + g);

    const uint4* __restrict__ Ur = (const uint4*)(U + (long)s * UROWP);
    const float* __restrict__ ear = eat + (long)g * 16;

    // this lane's 4 edge-attr coefficients: f = 4c + fi
    float eaf0 = __ldg(ear + fi);
    float eaf1 = __ldg(ear + 4 + fi);
    float eaf2 = __ldg(ear + 8 + fi);
    float eaf3 = __ldg(ear + 12 + fi);
    float eaf[4] = {eaf0, eaf1, eaf2, eaf3};

    float acc[8];
    // bias block: only lanes 0 (h=0) and 1 (h=1) add it (once per group)
    if (j < 2) {
        uint4 u = __ldg(Ur + 32 + j);
        const __half2* hh = (const __half2*)&u;
#pragma unroll
        for (int k = 0; k < 4; ++k) {
            float2 f2 = __half22float2(hh[k]);
            acc[2 * k + 0] = f2.x;
            acc[2 * k + 1] = f2.y;
        }
    } else {
#pragma unroll
        for (int k = 0; k < 8; ++k) acc[k] = 0.0f;
    }

#pragma unroll
    for (int c = 0; c < 4; ++c) {
        uint4 u = __ldg(Ur + c * 8 + j);    // full 128B line per octet
        float er = eaf[c];
        const __half2* hh = (const __half2*)&u;
#pragma unroll
        for (int k = 0; k < 4; ++k) {
            float2 f2 = __half22float2(hh[k]);
            acc[2 * k + 0] += er * f2.x;
            acc[2 * k + 1] += er * f2.y;
        }
    }

    // reduce the 4 partial sums per o-half group ({j:0,2,4,6} and {1,3,5,7})
#pragma unroll
    for (int k = 0; k < 8; ++k)
        acc[k] += __shfl_xor_sync(0xffffffffu, acc[k], 2);
#pragma unroll
    for (int k = 0; k < 8; ++k)
        acc[k] += __shfl_xor_sync(0xffffffffu, acc[k], 4);

    if (valid && j < 2) {
        int d = __ldg(ei + E + g);
        float* base = &agg[d * 16 + 8 * h];
        red4(base,     acc[0], acc[1], acc[2], acc[3]);
        red4(base + 4, acc[4], acc[5], acc[6], acc[7]);
    }
}

// ---------------------------------------------------------------------------
// final: 2 lanes per node; lane l computes outputs 16l..16l+15
// ---------------------------------------------------------------------------
__global__ __launch_bounds__(256) void final_kernel(
    const float* __restrict__ w_lin,
    const float* __restrict__ b_lin,
    float* __restrict__ out, int N) {
    __shared__ __align__(16) float wl[32 * 32];
    __shared__ float bl[32];
    for (int k = threadIdx.x; k < 1024; k += 256) wl[k] = w_lin[k];
    if (threadIdx.x < 32) bl[threadIdx.x] = b_lin[threadIdx.x];
    __syncthreads();

    int t = blockIdx.x * 256 + threadIdx.x;
    int n = t >> 1;
    int l = t & 1;
    if (n >= N) return;

    float s[32];
    {
        const float4* ga = (const float4*)(&g_agg[0][n * 16]);
        const float4* gb = (const float4*)(&g_agg[1][n * 16]);
#pragma unroll
        for (int j = 0; j < 4; ++j) {
            float4 va = ga[j];
            s[4 * j + 0] = sigmoidf(va.x); s[4 * j + 1] = sigmoidf(va.y);
            s[4 * j + 2] = sigmoidf(va.z); s[4 * j + 3] = sigmoidf(va.w);
        }
#pragma unroll
        for (int j = 0; j < 4; ++j) {
            float4 vb = gb[j];
            s[16 + 4 * j + 0] = sigmoidf(vb.x); s[16 + 4 * j + 1] = sigmoidf(vb.y);
            s[16 + 4 * j + 2] = sigmoidf(vb.z); s[16 + 4 * j + 3] = sigmoidf(vb.w);
        }
    }

    float4 acc[4];
#pragma unroll
    for (int j = 0; j < 4; ++j) {
        int o = 16 * l + 4 * j;
        acc[j] = make_float4(bl[o], bl[o + 1], bl[o + 2], bl[o + 3]);
    }
#pragma unroll
    for (int k = 0; k < 32; ++k) {
        float sk = s[k];
        const float4* w4 = (const float4*)(wl + k * 32 + 16 * l);
#pragma unroll
        for (int j = 0; j < 4; ++j) {
            float4 w = w4[j];
            acc[j].x += sk * w.x;
            acc[j].y += sk * w.y;
            acc[j].z += sk * w.z;
            acc[j].w += sk * w.w;
        }
    }

    float4* o4 = (float4*)(out + n * 32 + 16 * l);
#pragma unroll
    for (int j = 0; j < 4; ++j)
        o4[j] = make_float4(sigmoidf(acc[j].x), sigmoidf(acc[j].y),
                            sigmoidf(acc[j].z), sigmoidf(acc[j].w));
}

// ---------------------------------------------------------------------------
extern "C" void kernel_launch(void* const* d_in, const int* in_sizes, int n_in,
                              void* d_out, int out_size) {
    const float* x_indivi = (const float*)d_in[0];
    const float* x_src_a  = (const float*)d_in[1];
    const float* x_src_b  = (const float*)d_in[2];
    const int*   ei_a     = (const int*)d_in[3];
    const int*   ei_b     = (const int*)d_in[4];
    const float* ea_a     = (const float*)d_in[5];
    const float* ea_b     = (const float*)d_in[6];
    const float* wm_a     = (const float*)d_in[7];
    const float* bm_a     = (const float*)d_in[8];
    const float* root_a   = (const float*)d_in[9];
    const float* bias_a   = (const float*)d_in[10];
    const float* wm_b     = (const float*)d_in[11];
    const float* bm_b     = (const float*)d_in[12];
    const float* root_b   = (const float*)d_in[13];
    const float* bias_b   = (const float*)d_in[14];
    const float* w_lin    = (const float*)d_in[15];
    const float* b_lin    = (const float*)d_in[16];
    float* out = (float*)d_out;

    int N = in_sizes[0] / 16;
    int E = in_sizes[3] / 2;   // edge_index is [2, E]

    float* agg_base;  __half* U_base;
    cudaGetSymbolAddress((void**)&agg_base, g_agg);
    cudaGetSymbolAddress((void**)&U_base, g_U);
    float*  agg_a = agg_base;
    float*  agg_b = agg_base + NMAX * 16;
    __half* U_a = U_base;
    __half* U_b = U_base + (long)NMAX * UROWP;

    int nb2 = (2 * N + 255) / 256;
    int eb8 = (int)(((long)8 * E + 255) / 256);

    // launch 1: init
    init_kernel<<<nb2, 256>>>(x_indivi, root_a, bias_a, root_b, bias_b, N);
    // launch 2,3: U tables
    u_kernel<<<nb2, 256>>>(x_src_a, wm_a, bm_a, U_a, N);
    u_kernel<<<nb2, 256>>>(x_src_b, wm_b, bm_b, U_b, N);
    // launch 4: edge step a  (profiler lands here)
    edge_kernel<<<eb8, 256>>>(ei_a, ea_a, U_a, agg_a, E);
    // launch 5: edge step b
    edge_kernel<<<eb8, 256>>>(ei_b, ea_b, U_b, agg_b, E);
    // launch 6: final
    final_kernel<<<nb2, 256>>>(w_lin, b_lin, out, N);
}

// round 11
// speedup vs baseline: 2.1481x; 1.2754x over previous
#include <cuda_runtime.h>
#include <cuda_fp16.h>

// ---------------------------------------------------------------------------
// HMPNN layer, R9: R7 coalesced edge gather (8 lanes/edge, 640B padded fp16 U
// rows) kept; prep consolidated into one broadcast-friendly launch; edge steps
// merged into one launch.
//   U[n,f,o] = sum_i x_src[n,i] * w_msg[f,i,o]   (f=16 block = xj@b_msg)
//   msg[e,o] = U[src,16,o] + sum_f ea[e,f] * U[src,f,o]
//   agg[n]   = segment_sum(msg) + x_indivi @ root + bias
//   out      = sigmoid( concat(sig(agg_a), sig(agg_b)) @ w_lin + b_lin )
// ---------------------------------------------------------------------------

#define NMAX 50000
#define UROWP 320            // padded row: 320 halves = 640B = 5 x 128B lines

__device__ float  g_agg[2][NMAX * 16];
__device__ __align__(128) __half g_U[2][NMAX * UROWP];

__device__ __forceinline__ void red4(float* p, float a, float b, float c, float d) {
    asm volatile("red.global.add.v4.f32 [%0], {%1,%2,%3,%4};"
                 :: "l"(p), "f"(a), "f"(b), "f"(c), "f"(d) : "memory");
}
__device__ __forceinline__ float sigmoidf(float x) {
    return 1.0f / (1.0f + __expf(-x));
}

// ---------------------------------------------------------------------------
// prep: grid.y roles.
//  role 0: init  — 2 threads/node (lane = step): agg = bias + x_indivi@root
//  role 1: U_a   — 2 threads/node (lane = o-half), broadcast-friendly LDS
//  role 2: U_b
// ---------------------------------------------------------------------------
__global__ __launch_bounds__(256) void prep_kernel(
    const float* __restrict__ x_indivi,
    const float* __restrict__ xs_a, const float* __restrict__ xs_b,
    const float* __restrict__ root_a, const float* __restrict__ bias_a,
    const float* __restrict__ root_b, const float* __restrict__ bias_b,
    const float* __restrict__ wm_a, const float* __restrict__ bm_a,
    const float* __restrict__ wm_b, const float* __restrict__ bm_b,
    int N) {
    const int role = blockIdx.y;
    int t = blockIdx.x * 256 + threadIdx.x;
    int n = t >> 1;
    int l = t & 1;

    if (role == 0) {
        if (n >= N) return;
        const float* __restrict__ root = l ? root_b : root_a;
        const float* __restrict__ bias = l ? bias_b : bias_a;

        float x[16];
        const float4* xr = (const float4*)(x_indivi + n * 16);
#pragma unroll
        for (int j = 0; j < 4; ++j) {
            float4 v = xr[j];
            x[4 * j + 0] = v.x; x[4 * j + 1] = v.y;
            x[4 * j + 2] = v.z; x[4 * j + 3] = v.w;
        }
        float s[16];
#pragma unroll
        for (int o = 0; o < 16; ++o) s[o] = __ldg(bias + o);
#pragma unroll
        for (int i = 0; i < 16; ++i) {
            float xi = x[i];
            const float4* rr = (const float4*)(root + i * 16);
#pragma unroll
            for (int j = 0; j < 4; ++j) {
                float4 w = __ldg(rr + j);
                s[4 * j + 0] += xi * w.x;
                s[4 * j + 1] += xi * w.y;
                s[4 * j + 2] += xi * w.z;
                s[4 * j + 3] += xi * w.w;
            }
        }
        float4* dst = (float4*)(&g_agg[l][n * 16]);
#pragma unroll
        for (int j = 0; j < 4; ++j)
            dst[j] = make_float4(s[4 * j], s[4 * j + 1], s[4 * j + 2], s[4 * j + 3]);
        return;
    }

    // roles 1,2: U table. lane l = o-half; both lanes read the same weight
    // row base (l only offsets by a constant 32B) -> broadcast-pair LDS.
    const float* __restrict__ xs = (role == 1) ? xs_a : xs_b;
    const float* __restrict__ wm = (role == 1) ? wm_a : wm_b;
    const float* __restrict__ bm = (role == 1) ? bm_a : bm_b;
    __half* __restrict__ U = g_U[role - 1];

    __shared__ __align__(16) float Ws[17 * 256];   // [f][i][o], f=16 = b_msg
    for (int k = threadIdx.x; k < 4096; k += 256) Ws[k] = wm[k];
    if (threadIdx.x < 256) Ws[4096 + threadIdx.x] = bm[threadIdx.x];
    __syncthreads();

    if (n >= N) return;

    float x[16];
    const float4* xr = (const float4*)(xs + n * 16);
#pragma unroll
    for (int j = 0; j < 4; ++j) {
        float4 v = xr[j];
        x[4 * j + 0] = v.x; x[4 * j + 1] = v.y;
        x[4 * j + 2] = v.z; x[4 * j + 3] = v.w;
    }

    __half* Urow = U + (long)n * UROWP;
#pragma unroll 1
    for (int f = 0; f < 17; ++f) {
        const float* Wf = Ws + f * 256 + l * 8;     // this lane's o-half
        float acc[8];
#pragma unroll
        for (int o = 0; o < 8; ++o) acc[o] = 0.0f;
#pragma unroll
        for (int i = 0; i < 16; ++i) {
            float xi = x[i];
            const float4* wr = (const float4*)(Wf + i * 16);
            float4 w0 = wr[0];
            float4 w1 = wr[1];
            acc[0] += xi * w0.x; acc[1] += xi * w0.y;
            acc[2] += xi * w0.z; acc[3] += xi * w0.w;
            acc[4] += xi * w1.x; acc[5] += xi * w1.y;
            acc[6] += xi * w1.z; acc[7] += xi * w1.w;
        }
        __half2 h[4];
#pragma unroll
        for (int j = 0; j < 4; ++j)
            h[j] = __floats2half2_rn(acc[2 * j], acc[2 * j + 1]);
        *(uint4*)(Urow + f * 16 + l * 8) = *(const uint4*)&h[0];
    }
}

// ---------------------------------------------------------------------------
// edge: blockIdx.y = step. 8 lanes per edge; round c: octet loads one full
// 128B line (f-blocks 4c..4c+3); lane j owns f=4c+(j>>1), o-half j&1.
// Bias block: lanes 0/1. Butterfly shfl_xor(2),(4) reduces; lanes 0/1 scatter.
// ---------------------------------------------------------------------------
__global__ __launch_bounds__(256) void edge_kernel(
    const int* __restrict__ ei_a, const int* __restrict__ ei_b,
    const float* __restrict__ eat_a, const float* __restrict__ eat_b,
    int E) {
    const int step = blockIdx.y;
    const int*   __restrict__ ei  = step ? ei_b  : ei_a;
    const float* __restrict__ eat = step ? eat_b : eat_a;
    const __half* __restrict__ U  = g_U[step];
    float* __restrict__ agg       = g_agg[step];

    int t = blockIdx.x * 256 + threadIdx.x;
    int g = t >> 3;                 // edge index
    int j = t & 7;                  // octet lane
    bool valid = (g < E);
    if (g >= E) g = E - 1;          // clamp; keep lanes converged for shfl

    int h = j & 1;                  // o-half
    int fi = j >> 1;                // f offset within each 4-block

    int s = __ldg(ei + g);

    const uint4* __restrict__ Ur = (const uint4*)(U + (long)s * UROWP);
    const float* __restrict__ ear = eat + (long)g * 16;

    float eaf[4] = {__ldg(ear + fi),     __ldg(ear + 4 + fi),
                    __ldg(ear + 8 + fi), __ldg(ear + 12 + fi)};

    float acc[8];
    if (j < 2) {                    // bias block (f=16), once per o-half group
        uint4 u = __ldg(Ur + 32 + j);
        const __half2* hh = (const __half2*)&u;
#pragma unroll
        for (int k = 0; k < 4; ++k) {
            float2 f2 = __half22float2(hh[k]);
            acc[2 * k + 0] = f2.x;
            acc[2 * k + 1] = f2.y;
        }
    } else {
#pragma unroll
        for (int k = 0; k < 8; ++k) acc[k] = 0.0f;
    }

#pragma unroll
    for (int c = 0; c < 4; ++c) {
        uint4 u = __ldg(Ur + c * 8 + j);    // full 128B line per octet
        float er = eaf[c];
        const __half2* hh = (const __half2*)&u;
#pragma unroll
        for (int k = 0; k < 4; ++k) {
            float2 f2 = __half22float2(hh[k]);
            acc[2 * k + 0] += er * f2.x;
            acc[2 * k + 1] += er * f2.y;
        }
    }

#pragma unroll
    for (int k = 0; k < 8; ++k)
        acc[k] += __shfl_xor_sync(0xffffffffu, acc[k], 2);
#pragma unroll
    for (int k = 0; k < 8; ++k)
        acc[k] += __shfl_xor_sync(0xffffffffu, acc[k], 4);

    if (valid && j < 2) {
        int d = __ldg(ei + E + g);
        float* base = &agg[d * 16 + 8 * h];
        red4(base,     acc[0], acc[1], acc[2], acc[3]);
        red4(base + 4, acc[4], acc[5], acc[6], acc[7]);
    }
}

// ---------------------------------------------------------------------------
// final: 2 lanes per node; lane l computes outputs 16l..16l+15
// ---------------------------------------------------------------------------
__global__ __launch_bounds__(256) void final_kernel(
    const float* __restrict__ w_lin,
    const float* __restrict__ b_lin,
    float* __restrict__ out, int N) {
    __shared__ __align__(16) float wl[32 * 32];
    __shared__ float bl[32];
    for (int k = threadIdx.x; k < 1024; k += 256) wl[k] = w_lin[k];
    if (threadIdx.x < 32) bl[threadIdx.x] = b_lin[threadIdx.x];
    __syncthreads();

    int t = blockIdx.x * 256 + threadIdx.x;
    int n = t >> 1;
    int l = t & 1;
    if (n >= N) return;

    float s[32];
    {
        const float4* ga = (const float4*)(&g_agg[0][n * 16]);
        const float4* gb = (const float4*)(&g_agg[1][n * 16]);
#pragma unroll
        for (int j = 0; j < 4; ++j) {
            float4 va = ga[j];
            s[4 * j + 0] = sigmoidf(va.x); s[4 * j + 1] = sigmoidf(va.y);
            s[4 * j + 2] = sigmoidf(va.z); s[4 * j + 3] = sigmoidf(va.w);
        }
#pragma unroll
        for (int j = 0; j < 4; ++j) {
            float4 vb = gb[j];
            s[16 + 4 * j + 0] = sigmoidf(vb.x); s[16 + 4 * j + 1] = sigmoidf(vb.y);
            s[16 + 4 * j + 2] = sigmoidf(vb.z); s[16 + 4 * j + 3] = sigmoidf(vb.w);
        }
    }

    float4 acc[4];
#pragma unroll
    for (int j = 0; j < 4; ++j) {
        int o = 16 * l + 4 * j;
        acc[j] = make_float4(bl[o], bl[o + 1], bl[o + 2], bl[o + 3]);
    }
#pragma unroll
    for (int k = 0; k < 32; ++k) {
        float sk = s[k];
        const float4* w4 = (const float4*)(wl + k * 32 + 16 * l);
#pragma unroll
        for (int j = 0; j < 4; ++j) {
            float4 w = w4[j];
            acc[j].x += sk * w.x;
            acc[j].y += sk * w.y;
            acc[j].z += sk * w.z;
            acc[j].w += sk * w.w;
        }
    }

    float4* o4 = (float4*)(out + n * 32 + 16 * l);
#pragma unroll
    for (int j = 0; j < 4; ++j)
        o4[j] = make_float4(sigmoidf(acc[j].x), sigmoidf(acc[j].y),
                            sigmoidf(acc[j].z), sigmoidf(acc[j].w));
}

// ---------------------------------------------------------------------------
extern "C" void kernel_launch(void* const* d_in, const int* in_sizes, int n_in,
                              void* d_out, int out_size) {
    const float* x_indivi = (const float*)d_in[0];
    const float* x_src_a  = (const float*)d_in[1];
    const float* x_src_b  = (const float*)d_in[2];
    const int*   ei_a     = (const int*)d_in[3];
    const int*   ei_b     = (const int*)d_in[4];
    const float* ea_a     = (const float*)d_in[5];
    const float* ea_b     = (const float*)d_in[6];
    const float* wm_a     = (const float*)d_in[7];
    const float* bm_a     = (const float*)d_in[8];
    const float* root_a   = (const float*)d_in[9];
    const float* bias_a   = (const float*)d_in[10];
    const float* wm_b     = (const float*)d_in[11];
    const float* bm_b     = (const float*)d_in[12];
    const float* root_b   = (const float*)d_in[13];
    const float* bias_b   = (const float*)d_in[14];
    const float* w_lin    = (const float*)d_in[15];
    const float* b_lin    = (const float*)d_in[16];
    float* out = (float*)d_out;

    int N = in_sizes[0] / 16;
    int E = in_sizes[3] / 2;   // edge_index is [2, E]

    int nb2 = (2 * N + 255) / 256;
    int eb8 = (int)(((long)8 * E + 255) / 256);

    // launch 1: prep (init + both U tables)
    prep_kernel<<<dim3(nb2, 3), 256>>>(x_indivi, x_src_a, x_src_b,
                                       root_a, bias_a, root_b, bias_b,
                                       wm_a, bm_a, wm_b, bm_b, N);
    // launch 2: both edge steps
    edge_kernel<<<dim3(eb8, 2), 256>>>(ei_a, ei_b, ea_a, ea_b, E);
    // launch 3: final
    final_kernel<<<nb2, 256>>>(w_lin, b_lin, out, N);
}

// round 12
// speedup vs baseline: 2.2249x; 1.0357x over previous
#include <cuda_runtime.h>
#include <cuda_fp16.h>

// ---------------------------------------------------------------------------
// HMPNN layer, R11: R9 + prep amortization (4 nodes/thread in U build, weight
// LDS reused 4x -> prep no longer LDS-issue bound).
//   U[n,f,o] = sum_i x_src[n,i] * w_msg[f,i,o]   (f=16 block = xj@b_msg)
//   msg[e,o] = U[src,16,o] + sum_f ea[e,f] * U[src,f,o]
//   agg[n]   = segment_sum(msg) + x_indivi @ root + bias
//   out      = sigmoid( concat(sig(agg_a), sig(agg_b)) @ w_lin + b_lin )
// ---------------------------------------------------------------------------

#define NMAX 50000
#define UROWP 320            // padded row: 320 halves = 640B = 5 x 128B lines

__device__ float  g_agg[2][NMAX * 16];
__device__ __align__(128) __half g_U[2][NMAX * UROWP];

__device__ __forceinline__ void red4(float* p, float a, float b, float c, float d) {
    asm volatile("red.global.add.v4.f32 [%0], {%1,%2,%3,%4};"
                 :: "l"(p), "f"(a), "f"(b), "f"(c), "f"(d) : "memory");
}
__device__ __forceinline__ float sigmoidf(float x) {
    return 1.0f / (1.0f + __expf(-x));
}

// ---------------------------------------------------------------------------
// prep: grid.y roles.
//  role 0: init — 2 threads/node (lane = step): agg = bias + x_indivi@root
//  role 1: U_a  — 2 threads per 4-node quad (lane = o-half), weights reused 4x
//  role 2: U_b
// ---------------------------------------------------------------------------
__global__ __launch_bounds__(256) void prep_kernel(
    const float* __restrict__ x_indivi,
    const float* __restrict__ xs_a, const float* __restrict__ xs_b,
    const float* __restrict__ root_a, const float* __restrict__ bias_a,
    const float* __restrict__ root_b, const float* __restrict__ bias_b,
    const float* __restrict__ wm_a, const float* __restrict__ bm_a,
    const float* __restrict__ wm_b, const float* __restrict__ bm_b,
    int N, int nblk_u) {
    const int role = blockIdx.y;

    if (role == 0) {
        int t = blockIdx.x * 256 + threadIdx.x;
        int n = t >> 1;
        int l = t & 1;
        if (n >= N) return;
        const float* __restrict__ root = l ? root_b : root_a;
        const float* __restrict__ bias = l ? bias_b : bias_a;

        float x[16];
        const float4* xr = (const float4*)(x_indivi + n * 16);
#pragma unroll
        for (int j = 0; j < 4; ++j) {
            float4 v = xr[j];
            x[4 * j + 0] = v.x; x[4 * j + 1] = v.y;
            x[4 * j + 2] = v.z; x[4 * j + 3] = v.w;
        }
        float s[16];
#pragma unroll
        for (int o = 0; o < 16; ++o) s[o] = __ldg(bias + o);
#pragma unroll
        for (int i = 0; i < 16; ++i) {
            float xi = x[i];
            const float4* rr = (const float4*)(root + i * 16);
#pragma unroll
            for (int j = 0; j < 4; ++j) {
                float4 w = __ldg(rr + j);
                s[4 * j + 0] += xi * w.x;
                s[4 * j + 1] += xi * w.y;
                s[4 * j + 2] += xi * w.z;
                s[4 * j + 3] += xi * w.w;
            }
        }
        float4* dst = (float4*)(&g_agg[l][n * 16]);
#pragma unroll
        for (int j = 0; j < 4; ++j)
            dst[j] = make_float4(s[4 * j], s[4 * j + 1], s[4 * j + 2], s[4 * j + 3]);
        return;
    }

    // roles 1,2: U table build. Uniform early-exit for excess blocks.
    if (blockIdx.x >= nblk_u) return;

    const float* __restrict__ xs = (role == 1) ? xs_a : xs_b;
    const float* __restrict__ wm = (role == 1) ? wm_a : wm_b;
    const float* __restrict__ bm = (role == 1) ? bm_a : bm_b;
    __half* __restrict__ U = g_U[role - 1];

    __shared__ __align__(16) float Ws[17 * 256];   // [f][i][o], f=16 = b_msg
    for (int k = threadIdx.x; k < 4096; k += 256) Ws[k] = wm[k];
    if (threadIdx.x < 256) Ws[4096 + threadIdx.x] = bm[threadIdx.x];
    __syncthreads();

    int t = blockIdx.x * 256 + threadIdx.x;
    int g = t >> 1;                 // 4-node quad index
    int l = t & 1;                  // o-half
    int n0 = g * 4;
    if (n0 >= N) return;

    // load x for 4 nodes (clamped; duplicate writes are identical -> benign,
    // but we guard stores anyway)
    float x[4][16];
#pragma unroll
    for (int k = 0; k < 4; ++k) {
        int nk = min(n0 + k, N - 1);
        const float4* xr = (const float4*)(xs + nk * 16);
#pragma unroll
        for (int j = 0; j < 4; ++j) {
            float4 v = xr[j];
            x[k][4 * j + 0] = v.x; x[k][4 * j + 1] = v.y;
            x[k][4 * j + 2] = v.z; x[k][4 * j + 3] = v.w;
        }
    }

#pragma unroll 1
    for (int f = 0; f < 17; ++f) {
        const float* Wf = Ws + f * 256 + l * 8;     // this lane's o-half
        float acc[4][8];
#pragma unroll
        for (int k = 0; k < 4; ++k)
#pragma unroll
            for (int o = 0; o < 8; ++o) acc[k][o] = 0.0f;

#pragma unroll
        for (int i = 0; i < 16; ++i) {
            const float4* wr = (const float4*)(Wf + i * 16);
            float4 w0 = wr[0];
            float4 w1 = wr[1];
#pragma unroll
            for (int k = 0; k < 4; ++k) {
                float xi = x[k][i];
                acc[k][0] += xi * w0.x; acc[k][1] += xi * w0.y;
                acc[k][2] += xi * w0.z; acc[k][3] += xi * w0.w;
                acc[k][4] += xi * w1.x; acc[k][5] += xi * w1.y;
                acc[k][6] += xi * w1.z; acc[k][7] += xi * w1.w;
            }
        }

#pragma unroll
        for (int k = 0; k < 4; ++k) {
            if (n0 + k < N) {
                __half2 h[4];
#pragma unroll
                for (int j = 0; j < 4; ++j)
                    h[j] = __floats2half2_rn(acc[k][2 * j], acc[k][2 * j + 1]);
                *(uint4*)(U + (long)(n0 + k) * UROWP + f * 16 + l * 8) =
                    *(const uint4*)&h[0];
            }
        }
    }
}

// ---------------------------------------------------------------------------
// edge: blockIdx.y = step. 8 lanes per edge; round c: octet loads one full
// 128B line (f-blocks 4c..4c+3); lane j owns f=4c+(j>>1), o-half j&1.
// Bias block: lanes 0/1. Butterfly shfl_xor(2),(4) reduces; lanes 0/1 scatter.
// ---------------------------------------------------------------------------
__global__ __launch_bounds__(256) void edge_kernel(
    const int* __restrict__ ei_a, const int* __restrict__ ei_b,
    const float* __restrict__ eat_a, const float* __restrict__ eat_b,
    int E) {
    const int step = blockIdx.y;
    const int*   __restrict__ ei  = step ? ei_b  : ei_a;
    const float* __restrict__ eat = step ? eat_b : eat_a;
    const __half* __restrict__ U  = g_U[step];
    float* __restrict__ agg       = g_agg[step];

    int t = blockIdx.x * 256 + threadIdx.x;
    int g = t >> 3;                 // edge index
    int j = t & 7;                  // octet lane
    bool valid = (g < E);
    if (g >= E) g = E - 1;          // clamp; keep lanes converged for shfl

    int h = j & 1;                  // o-half
    int fi = j >> 1;                // f offset within each 4-block

    int s = __ldg(ei + g);

    const uint4* __restrict__ Ur = (const uint4*)(U + (long)s * UROWP);
    const float* __restrict__ ear = eat + (long)g * 16;

    float eaf[4] = {__ldg(ear + fi),     __ldg(ear + 4 + fi),
                    __ldg(ear + 8 + fi), __ldg(ear + 12 + fi)};

    float acc[8];
    if (j < 2) {                    // bias block (f=16), once per o-half group
        uint4 u = __ldg(Ur + 32 + j);
        const __half2* hh = (const __half2*)&u;
#pragma unroll
        for (int k = 0; k < 4; ++k) {
            float2 f2 = __half22float2(hh[k]);
            acc[2 * k + 0] = f2.x;
            acc[2 * k + 1] = f2.y;
        }
    } else {
#pragma unroll
        for (int k = 0; k < 8; ++k) acc[k] = 0.0f;
    }

#pragma unroll
    for (int c = 0; c < 4; ++c) {
        uint4 u = __ldg(Ur + c * 8 + j);    // full 128B line per octet
        float er = eaf[c];
        const __half2* hh = (const __half2*)&u;
#pragma unroll
        for (int k = 0; k < 4; ++k) {
            float2 f2 = __half22float2(hh[k]);
            acc[2 * k + 0] += er * f2.x;
            acc[2 * k + 1] += er * f2.y;
        }
    }

#pragma unroll
    for (int k = 0; k < 8; ++k)
        acc[k] += __shfl_xor_sync(0xffffffffu, acc[k], 2);
#pragma unroll
    for (int k = 0; k < 8; ++k)
        acc[k] += __shfl_xor_sync(0xffffffffu, acc[k], 4);

    if (valid && j < 2) {
        int d = __ldg(ei + E + g);
        float* base = &agg[d * 16 + 8 * h];
        red4(base,     acc[0], acc[1], acc[2], acc[3]);
        red4(base + 4, acc[4], acc[5], acc[6], acc[7]);
    }
}

// ---------------------------------------------------------------------------
// final: 2 lanes per node; lane l computes outputs 16l..16l+15
// ---------------------------------------------------------------------------
__global__ __launch_bounds__(256) void final_kernel(
    const float* __restrict__ w_lin,
    const float* __restrict__ b_lin,
    float* __restrict__ out, int N) {
    __shared__ __align__(16) float wl[32 * 32];
    __shared__ float bl[32];
    for (int k = threadIdx.x; k < 1024; k += 256) wl[k] = w_lin[k];
    if (threadIdx.x < 32) bl[threadIdx.x] = b_lin[threadIdx.x];
    __syncthreads();

    int t = blockIdx.x * 256 + threadIdx.x;
    int n = t >> 1;
    int l = t & 1;
    if (n >= N) return;

    float s[32];
    {
        const float4* ga = (const float4*)(&g_agg[0][n * 16]);
        const float4* gb = (const float4*)(&g_agg[1][n * 16]);
#pragma unroll
        for (int j = 0; j < 4; ++j) {
            float4 va = ga[j];
            s[4 * j + 0] = sigmoidf(va.x); s[4 * j + 1] = sigmoidf(va.y);
            s[4 * j + 2] = sigmoidf(va.z); s[4 * j + 3] = sigmoidf(va.w);
        }
#pragma unroll
        for (int j = 0; j < 4; ++j) {
            float4 vb = gb[j];
            s[16 + 4 * j + 0] = sigmoidf(vb.x); s[16 + 4 * j + 1] = sigmoidf(vb.y);
            s[16 + 4 * j + 2] = sigmoidf(vb.z); s[16 + 4 * j + 3] = sigmoidf(vb.w);
        }
    }

    float4 acc[4];
#pragma unroll
    for (int j = 0; j < 4; ++j) {
        int o = 16 * l + 4 * j;
        acc[j] = make_float4(bl[o], bl[o + 1], bl[o + 2], bl[o + 3]);
    }
#pragma unroll
    for (int k = 0; k < 32; ++k) {
        float sk = s[k];
        const float4* w4 = (const float4*)(wl + k * 32 + 16 * l);
#pragma unroll
        for (int j = 0; j < 4; ++j) {
            float4 w = w4[j];
            acc[j].x += sk * w.x;
            acc[j].y += sk * w.y;
            acc[j].z += sk * w.z;
            acc[j].w += sk * w.w;
        }
    }

    float4* o4 = (float4*)(out + n * 32 + 16 * l);
#pragma unroll
    for (int j = 0; j < 4; ++j)
        o4[j] = make_float4(sigmoidf(acc[j].x), sigmoidf(acc[j].y),
                            sigmoidf(acc[j].z), sigmoidf(acc[j].w));
}

// ---------------------------------------------------------------------------
extern "C" void kernel_launch(void* const* d_in, const int* in_sizes, int n_in,
                              void* d_out, int out_size) {
    const float* x_indivi = (const float*)d_in[0];
    const float* x_src_a  = (const float*)d_in[1];
    const float* x_src_b  = (const float*)d_in[2];
    const int*   ei_a     = (const int*)d_in[3];
    const int*   ei_b     = (const int*)d_in[4];
    const float* ea_a     = (const float*)d_in[5];
    const float* ea_b     = (const float*)d_in[6];
    const float* wm_a     = (const float*)d_in[7];
    const float* bm_a     = (const float*)d_in[8];
    const float* root_a   = (const float*)d_in[9];
    const float* bias_a   = (const float*)d_in[10];
    const float* wm_b     = (const float*)d_in[11];
    const float* bm_b     = (const float*)d_in[12];
    const float* root_b   = (const float*)d_in[13];
    const float* bias_b   = (const float*)d_in[14];
    const float* w_lin    = (const float*)d_in[15];
    const float* b_lin    = (const float*)d_in[16];
    float* out = (float*)d_out;

    int N = in_sizes[0] / 16;
    int E = in_sizes[3] / 2;   // edge_index is [2, E]

    int nb2 = (2 * N + 255) / 256;                      // role 0 blocks
    int nblk_u = (2 * ((N + 3) / 4) + 255) / 256;       // roles 1/2 blocks
    int eb8 = (int)(((long)8 * E + 255) / 256);

    // launch 1: prep (init + both U tables)
    prep_kernel<<<dim3(nb2, 3), 256>>>(x_indivi, x_src_a, x_src_b,
                                       root_a, bias_a, root_b, bias_b,
                                       wm_a, bm_a, wm_b, bm_b, N, nblk_u);
    // launch 2: both edge steps
    edge_kernel<<<dim3(eb8, 2), 256>>>(ei_a, ei_b, ea_a, ea_b, E);
    // launch 3: final
    final_kernel<<<nb2, 256>>>(w_lin, b_lin, out, N);
}